// round 1
// baseline (speedup 1.0000x reference)
#include <cuda_runtime.h>
#include <cuda_bf16.h>
#include <float.h>

// Problem constants
#define B_  16
#define C_  256
#define H_  128
#define W_  128
#define HW_ (H_ * W_)            // 16384
#define HW4_ (HW_ / 4)           // 4096
#define KSZ 7
#define PAD 3

// Scratch: channel-max map, channel-avg map, gate map (per batch, per pixel)
__device__ float g_max[B_ * HW_];   // 1 MiB
__device__ float g_avg[B_ * HW_];   // 1 MiB
__device__ float g_gate[B_ * HW_];  // 1 MiB

// ---------------------------------------------------------------------------
// K1: channel reduction. One thread per float4 pixel-group per batch.
// x layout: [B][C][H][W]. Threads across a warp cover consecutive w -> fully
// coalesced 128B transactions per c-iteration. Unroll 8 over channels for MLP.
// ---------------------------------------------------------------------------
__global__ void __launch_bounds__(256) reduce_kernel(const float* __restrict__ x) {
    int tid = blockIdx.x * 256 + threadIdx.x;     // 0 .. B_*HW4_-1 (65536)
    int b  = tid / HW4_;
    int pg = tid - b * HW4_;                      // float4 group within batch

    const float4* xb = reinterpret_cast<const float4*>(x + (size_t)b * C_ * HW_) + pg;

    float4 mx = make_float4(-FLT_MAX, -FLT_MAX, -FLT_MAX, -FLT_MAX);
    float4 sm = make_float4(0.f, 0.f, 0.f, 0.f);

    #pragma unroll 1
    for (int c = 0; c < C_; c += 8) {
        float4 v[8];
        #pragma unroll
        for (int u = 0; u < 8; u++) {
            v[u] = xb[(size_t)(c + u) * HW4_];
        }
        #pragma unroll
        for (int u = 0; u < 8; u++) {
            mx.x = fmaxf(mx.x, v[u].x); sm.x += v[u].x;
            mx.y = fmaxf(mx.y, v[u].y); sm.y += v[u].y;
            mx.z = fmaxf(mx.z, v[u].z); sm.z += v[u].z;
            mx.w = fmaxf(mx.w, v[u].w); sm.w += v[u].w;
        }
    }

    const float inv_c = 1.0f / (float)C_;
    sm.x *= inv_c; sm.y *= inv_c; sm.z *= inv_c; sm.w *= inv_c;

    reinterpret_cast<float4*>(g_max)[b * HW4_ + pg] = mx;
    reinterpret_cast<float4*>(g_avg)[b * HW4_ + pg] = sm;
}

// ---------------------------------------------------------------------------
// K2: 7x7 conv over [max, avg] 2-channel map + bias + hsigmoid -> gate map.
// One thread per pixel. Maps are 2 MiB total -> L2 resident. Tiny kernel.
// ---------------------------------------------------------------------------
__global__ void __launch_bounds__(256) gate_kernel(const float* __restrict__ conv_w,
                                                   const float* __restrict__ conv_b) {
    __shared__ float sw[2 * KSZ * KSZ];  // 98 weights
    __shared__ float sbias;
    if (threadIdx.x < 2 * KSZ * KSZ) sw[threadIdx.x] = conv_w[threadIdx.x];
    if (threadIdx.x == 0) sbias = conv_b[0];
    __syncthreads();

    int tid = blockIdx.x * 256 + threadIdx.x;     // 0 .. B_*HW_-1 (262144)
    int b = tid / HW_;
    int p = tid - b * HW_;
    int h = p / W_;
    int w = p - h * W_;

    const float* __restrict__ mp = g_max + b * HW_;
    const float* __restrict__ ap = g_avg + b * HW_;

    float acc = sbias;
    #pragma unroll
    for (int kh = 0; kh < KSZ; kh++) {
        int hh = h + kh - PAD;
        if (hh < 0 || hh >= H_) continue;
        int rowoff = hh * W_;
        #pragma unroll
        for (int kw = 0; kw < KSZ; kw++) {
            int ww = w + kw - PAD;
            if (ww < 0 || ww >= W_) continue;
            int q = rowoff + ww;
            acc = fmaf(sw[kh * KSZ + kw],            mp[q], acc);
            acc = fmaf(sw[49 + kh * KSZ + kw],       ap[q], acc);
        }
    }

    // hsigmoid: clip(acc + 3, 0, 6) / 6
    float g = fminf(fmaxf(acc + 3.0f, 0.0f), 6.0f) * (1.0f / 6.0f);
    g_gate[tid] = g;
}

// ---------------------------------------------------------------------------
// K3: out = x * gate (gate broadcast over channel dim). float4 streaming.
// Gate map is 1 MiB -> stays in L2, re-read 256x per batch for free.
// ---------------------------------------------------------------------------
__global__ void __launch_bounds__(256) mul_kernel(const float* __restrict__ x,
                                                  float* __restrict__ out) {
    long i4 = (long)blockIdx.x * 256 + threadIdx.x;   // 0 .. B_*C_*HW4_-1 (16777216)
    const long per_b = (long)C_ * HW4_;               // 1048576 float4s per batch
    int b   = (int)(i4 / per_b);
    long rem = i4 - (long)b * per_b;
    int pg  = (int)(rem % HW4_);                      // pixel float4-group

    float4 xv = reinterpret_cast<const float4*>(x)[i4];
    float4 gv = reinterpret_cast<const float4*>(g_gate)[b * HW4_ + pg];

    float4 ov;
    ov.x = xv.x * gv.x;
    ov.y = xv.y * gv.y;
    ov.z = xv.z * gv.z;
    ov.w = xv.w * gv.w;
    reinterpret_cast<float4*>(out)[i4] = ov;
}

// ---------------------------------------------------------------------------
extern "C" void kernel_launch(void* const* d_in, const int* in_sizes, int n_in,
                              void* d_out, int out_size) {
    const float* x      = (const float*)d_in[0];  // [16,256,128,128]
    const float* conv_w = (const float*)d_in[1];  // [1,2,7,7] = 98 floats
    const float* conv_b = (const float*)d_in[2];  // [1]
    float* out = (float*)d_out;

    // K1: B*HW/4 threads = 65536 -> 256 blocks x 256
    reduce_kernel<<<(B_ * HW4_) / 256, 256>>>(x);

    // K2: B*HW threads = 262144 -> 1024 blocks x 256
    gate_kernel<<<(B_ * HW_) / 256, 256>>>(conv_w, conv_b);

    // K3: B*C*HW/4 threads = 16777216 -> 65536 blocks x 256
    mul_kernel<<<(B_ * C_ * HW4_) / 256, 256>>>(x, out);
}